// round 4
// baseline (speedup 1.0000x reference)
#include <cuda_runtime.h>
#include <math.h>
#include <stdint.h>

#define BB 2
#define SS 2048
#define DD 1024
#define HH 16
#define DK 64
#define MTOT (BB*SS)

#define SCALE 12.5f                  // 100/sqrt(64)
#define INV_HS (1.0f/32768.0f)       // 1/(H*S)

// ---------------- scratch (static device globals; no allocation) -------------
__device__ float g_Q[MTOT*DD];
__device__ float g_K[MTOT*DD];
__device__ float g_V[MTOT*DD];
__device__ float g_C[MTOT*DD];

// ---------------- PTX helpers -------------------------------------------------
__device__ __forceinline__ uint32_t smem_u32(const void* p) {
    uint32_t a;
    asm("{ .reg .u64 t; cvta.to.shared.u64 t, %1; cvt.u32.u64 %0, t; }"
        : "=r"(a) : "l"(p));
    return a;
}

__device__ __forceinline__ uint32_t f32_to_tf32(float x) {
    uint32_t r;
    asm("cvt.rna.tf32.f32 %0, %1;" : "=r"(r) : "f"(x));
    return r;
}

__device__ __forceinline__ void mma_tf32(float c[4],
                                         uint32_t a0, uint32_t a1, uint32_t a2, uint32_t a3,
                                         uint32_t b0, uint32_t b1) {
    asm volatile(
        "mma.sync.aligned.m16n8k8.row.col.f32.tf32.tf32.f32 "
        "{%0,%1,%2,%3}, {%4,%5,%6,%7}, {%8,%9}, {%0,%1,%2,%3};"
        : "+f"(c[0]), "+f"(c[1]), "+f"(c[2]), "+f"(c[3])
        : "r"(a0), "r"(a1), "r"(a2), "r"(a3), "r"(b0), "r"(b1));
}

#define CP_ASYNC16(dst, src) \
    asm volatile("cp.async.cg.shared.global [%0], [%1], 16;" :: "r"(dst), "l"(src))
#define CP_COMMIT() asm volatile("cp.async.commit_group;" ::: "memory")
#define CP_WAIT1()  asm volatile("cp.async.wait_group 1;" ::: "memory")

// ---------------- zero mean_atp region ---------------------------------------
__global__ void zero_atp_kernel(float* __restrict__ atp) {
    int i = blockIdx.x * blockDim.x + threadIdx.x;
    if (i < BB*SS) atp[i] = 0.0f;
}

// ---------------- 3xTF32 mma.sync GEMM: Y[M,1024] = X @ W^T + b ---------------
// BM=BN=128, BK=32, 256 threads (8 warps, 2x4 warp grid), warp tile 64x32.
#define GK 1024
#define GN 1024
#define GBK 32
#define XS_LD 36                      // floats per row (pad 4)
#define TILE_FLOATS (128 * XS_LD)     // 4608
#define GEMM_SMEM (4 * TILE_FLOATS * 4)   // Xs[2] + Ws[2] = 73728 bytes

__global__ __launch_bounds__(256) void gemm_mma(
    const float* __restrict__ X, const float* __restrict__ W,
    const float* __restrict__ bias, float* __restrict__ Y)
{
    extern __shared__ float sh[];
    float* Xs = sh;                       // [2][128][XS_LD]
    float* Ws = sh + 2 * TILE_FLOATS;     // [2][128][XS_LD]

    const int t = threadIdx.x;
    const int w = t >> 5;
    const int lane = t & 31;
    const int g = lane >> 2;              // 0..7
    const int tig = lane & 3;             // 0..3
    const int warp_m = (w >> 2) * 64;     // 0 or 64
    const int warp_n = (w & 3) * 32;      // 0,32,64,96
    const int bm = blockIdx.y * 128;
    const int bn = blockIdx.x * 128;

    // global->shared load mapping: 4 rows of 8x16B per thread
    const int lrow = t >> 3;              // 0..31
    const int lcol = (t & 7) * 4;         // 0..28
    const uint32_t sbX = smem_u32(Xs);
    const uint32_t sbW = smem_u32(Ws);

    float acc[4][4][4];
#pragma unroll
    for (int mi = 0; mi < 4; ++mi)
#pragma unroll
        for (int ni = 0; ni < 4; ++ni)
#pragma unroll
            for (int j = 0; j < 4; ++j) acc[mi][ni][j] = 0.0f;

    const float* Xg = X + (size_t)(bm + lrow) * GK + lcol;
    const float* Wg = W + (size_t)(bn + lrow) * GK + lcol;

    // prologue: stage 0
#pragma unroll
    for (int ir = 0; ir < 4; ++ir) {
        uint32_t dX = sbX + ((lrow + 32 * ir) * XS_LD + lcol) * 4;
        uint32_t dW = sbW + ((lrow + 32 * ir) * XS_LD + lcol) * 4;
        CP_ASYNC16(dX, Xg + (size_t)(32 * ir) * GK);
        CP_ASYNC16(dW, Wg + (size_t)(32 * ir) * GK);
    }
    CP_COMMIT();

    const int NSTAGE = GK / GBK;   // 32
    for (int s = 0; s < NSTAGE; ++s) {
        const int buf = s & 1;
        if (s + 1 < NSTAGE) {
            const int nbuf = (s + 1) & 1;
            const size_t ko = (size_t)(s + 1) * GBK;
#pragma unroll
            for (int ir = 0; ir < 4; ++ir) {
                uint32_t dX = sbX + (nbuf * TILE_FLOATS + (lrow + 32 * ir) * XS_LD + lcol) * 4;
                uint32_t dW = sbW + (nbuf * TILE_FLOATS + (lrow + 32 * ir) * XS_LD + lcol) * 4;
                CP_ASYNC16(dX, Xg + (size_t)(32 * ir) * GK + ko);
                CP_ASYNC16(dW, Wg + (size_t)(32 * ir) * GK + ko);
            }
        }
        CP_COMMIT();
        CP_WAIT1();
        __syncthreads();

        const float* xb = Xs + buf * TILE_FLOATS;
        const float* wb = Ws + buf * TILE_FLOATS;

#pragma unroll
        for (int k8 = 0; k8 < GBK / 8; ++k8) {
            const int k0 = k8 * 8;
            uint32_t AH[4][4], AL[4][4], BH[4][2], BL[4][2];
#pragma unroll
            for (int mi = 0; mi < 4; ++mi) {
                const int r0 = warp_m + mi * 16;
                float v0 = xb[(r0 + g) * XS_LD + k0 + tig];
                float v1 = xb[(r0 + g + 8) * XS_LD + k0 + tig];
                float v2 = xb[(r0 + g) * XS_LD + k0 + tig + 4];
                float v3 = xb[(r0 + g + 8) * XS_LD + k0 + tig + 4];
                AH[mi][0] = f32_to_tf32(v0); AL[mi][0] = f32_to_tf32(v0 - __uint_as_float(AH[mi][0]));
                AH[mi][1] = f32_to_tf32(v1); AL[mi][1] = f32_to_tf32(v1 - __uint_as_float(AH[mi][1]));
                AH[mi][2] = f32_to_tf32(v2); AL[mi][2] = f32_to_tf32(v2 - __uint_as_float(AH[mi][2]));
                AH[mi][3] = f32_to_tf32(v3); AL[mi][3] = f32_to_tf32(v3 - __uint_as_float(AH[mi][3]));
            }
#pragma unroll
            for (int ni = 0; ni < 4; ++ni) {
                const int r0 = warp_n + ni * 8;
                float v0 = wb[(r0 + g) * XS_LD + k0 + tig];
                float v1 = wb[(r0 + g) * XS_LD + k0 + tig + 4];
                BH[ni][0] = f32_to_tf32(v0); BL[ni][0] = f32_to_tf32(v0 - __uint_as_float(BH[ni][0]));
                BH[ni][1] = f32_to_tf32(v1); BL[ni][1] = f32_to_tf32(v1 - __uint_as_float(BH[ni][1]));
            }
#pragma unroll
            for (int mi = 0; mi < 4; ++mi)
#pragma unroll
                for (int ni = 0; ni < 4; ++ni) {
                    mma_tf32(acc[mi][ni], AH[mi][0], AH[mi][1], AH[mi][2], AH[mi][3],
                             BH[ni][0], BH[ni][1]);
                    mma_tf32(acc[mi][ni], AH[mi][0], AH[mi][1], AH[mi][2], AH[mi][3],
                             BL[ni][0], BL[ni][1]);
                    mma_tf32(acc[mi][ni], AL[mi][0], AL[mi][1], AL[mi][2], AL[mi][3],
                             BH[ni][0], BH[ni][1]);
                }
        }
        __syncthreads();
    }

    // epilogue: write with bias
#pragma unroll
    for (int ni = 0; ni < 4; ++ni) {
        const int n = bn + warp_n + ni * 8 + 2 * tig;
        const float2 b2 = *(const float2*)(bias + n);
#pragma unroll
        for (int mi = 0; mi < 4; ++mi) {
            const int r0 = bm + warp_m + mi * 16;
            float2 o0, o1;
            o0.x = acc[mi][ni][0] + b2.x; o0.y = acc[mi][ni][1] + b2.y;
            o1.x = acc[mi][ni][2] + b2.x; o1.y = acc[mi][ni][3] + b2.y;
            *(float2*)(Y + (size_t)(r0 + g) * GN + n)     = o0;
            *(float2*)(Y + (size_t)(r0 + g + 8) * GN + n) = o1;
        }
    }
}

// ---------------- attention: two-pass exact softmax + PV + mean_atp ----------
#define BQ 64
#define BKT 64
#define PS_LD (BKT + 4)
#define SMEM_FLOATS (DK*BQ + DK*BKT + BKT*DK + BQ*PS_LD + 2*BQ)

__global__ __launch_bounds__(256) void attn_kernel(float* __restrict__ atp) {
    extern __shared__ float shf[];
    float* Qs   = shf;
    float* Ks   = Qs + DK*BQ;
    float* Vs   = Ks + DK*BKT;
    float* Ps   = Vs + BKT*DK;
    float* smm  = Ps + BQ*PS_LD;
    float* smil = smm + BQ;

    const int tid = threadIdx.x;
    const int bh = blockIdx.y;
    const int b = bh / HH, h = bh % HH;
    const int q0 = blockIdx.x * BQ;
    const int ty = tid >> 4;
    const int tx = tid & 15;
    const int tq = ty * 4;
    const int tk = tx * 4;
    const int lr = tid >> 2;
    const int lc4 = tid & 3;

    const float* Qg = g_Q + ((size_t)(b * SS + q0)) * DD + h * DK;
    const float* Kg = g_K + ((size_t)b * SS) * DD + h * DK;
    const float* Vg = g_V + ((size_t)b * SS) * DD + h * DK;

#pragma unroll
    for (int it = 0; it < 4; ++it) {
        int c4 = lc4 + it * 4;
        float4 v = *(const float4*)(Qg + (size_t)lr * DD + c4 * 4);
        Qs[(c4*4 + 0)*BQ + lr] = v.x; Qs[(c4*4 + 1)*BQ + lr] = v.y;
        Qs[(c4*4 + 2)*BQ + lr] = v.z; Qs[(c4*4 + 3)*BQ + lr] = v.w;
    }

    float m_loc[4], l_loc[4];
#pragma unroll
    for (int i = 0; i < 4; ++i) { m_loc[i] = -INFINITY; l_loc[i] = 0.0f; }

    for (int k0 = 0; k0 < SS; k0 += BKT) {
        __syncthreads();
#pragma unroll
        for (int it = 0; it < 4; ++it) {
            int c4 = lc4 + it * 4;
            float4 v = *(const float4*)(Kg + (size_t)(k0 + lr) * DD + c4 * 4);
            Ks[(c4*4 + 0)*BKT + lr] = v.x; Ks[(c4*4 + 1)*BKT + lr] = v.y;
            Ks[(c4*4 + 2)*BKT + lr] = v.z; Ks[(c4*4 + 3)*BKT + lr] = v.w;
        }
        __syncthreads();

        float s[4][4];
#pragma unroll
        for (int i = 0; i < 4; ++i)
#pragma unroll
            for (int j = 0; j < 4; ++j) s[i][j] = 0.0f;

#pragma unroll
        for (int d = 0; d < DK; ++d) {
            float a[4], bb[4];
            *(float4*)a  = *(const float4*)&Qs[d*BQ + tq];
            *(float4*)bb = *(const float4*)&Ks[d*BKT + tk];
#pragma unroll
            for (int i = 0; i < 4; ++i)
#pragma unroll
                for (int j = 0; j < 4; ++j)
                    s[i][j] = fmaf(a[i], bb[j], s[i][j]);
        }

#pragma unroll
        for (int i = 0; i < 4; ++i) {
            float mt = m_loc[i];
#pragma unroll
            for (int j = 0; j < 4; ++j) {
                s[i][j] *= SCALE;
                mt = fmaxf(mt, s[i][j]);
            }
            if (mt > m_loc[i]) {
                l_loc[i] *= __expf(m_loc[i] - mt);
                m_loc[i] = mt;
            }
#pragma unroll
            for (int j = 0; j < 4; ++j)
                l_loc[i] += __expf(s[i][j] - m_loc[i]);
        }
    }

#pragma unroll
    for (int i = 0; i < 4; ++i) {
        float m = m_loc[i], l = l_loc[i];
#pragma unroll
        for (int off = 8; off; off >>= 1) {
            float mo = __shfl_xor_sync(0xffffffffu, m, off);
            float lo = __shfl_xor_sync(0xffffffffu, l, off);
            float mn = fmaxf(m, mo);
            l = l * __expf(m - mn) + lo * __expf(mo - mn);
            m = mn;
        }
        if (tx == 0) { smm[tq + i] = m; smil[tq + i] = 1.0f / l; }
    }
    __syncthreads();

    float my_m[4], my_il[4];
#pragma unroll
    for (int i = 0; i < 4; ++i) { my_m[i] = smm[tq + i]; my_il[i] = smil[tq + i]; }

    float acc[4][4];
#pragma unroll
    for (int i = 0; i < 4; ++i)
#pragma unroll
        for (int j = 0; j < 4; ++j) acc[i][j] = 0.0f;

    for (int k0 = 0; k0 < SS; k0 += BKT) {
        __syncthreads();
#pragma unroll
        for (int it = 0; it < 4; ++it) {
            int c4 = lc4 + it * 4;
            float4 v = *(const float4*)(Kg + (size_t)(k0 + lr) * DD + c4 * 4);
            Ks[(c4*4 + 0)*BKT + lr] = v.x; Ks[(c4*4 + 1)*BKT + lr] = v.y;
            Ks[(c4*4 + 2)*BKT + lr] = v.z; Ks[(c4*4 + 3)*BKT + lr] = v.w;
            float4 ww = *(const float4*)(Vg + (size_t)(k0 + lr) * DD + c4 * 4);
            *(float4*)&Vs[lr*DK + c4*4] = ww;
        }
        __syncthreads();

        float s[4][4];
#pragma unroll
        for (int i = 0; i < 4; ++i)
#pragma unroll
            for (int j = 0; j < 4; ++j) s[i][j] = 0.0f;

#pragma unroll
        for (int d = 0; d < DK; ++d) {
            float a[4], bb[4];
            *(float4*)a  = *(const float4*)&Qs[d*BQ + tq];
            *(float4*)bb = *(const float4*)&Ks[d*BKT + tk];
#pragma unroll
            for (int i = 0; i < 4; ++i)
#pragma unroll
                for (int j = 0; j < 4; ++j)
                    s[i][j] = fmaf(a[i], bb[j], s[i][j]);
        }

#pragma unroll
        for (int i = 0; i < 4; ++i) {
            float4 p;
            p.x = __expf(s[i][0] * SCALE - my_m[i]) * my_il[i];
            p.y = __expf(s[i][1] * SCALE - my_m[i]) * my_il[i];
            p.z = __expf(s[i][2] * SCALE - my_m[i]) * my_il[i];
            p.w = __expf(s[i][3] * SCALE - my_m[i]) * my_il[i];
            *(float4*)&Ps[(tq + i)*PS_LD + tk] = p;
        }
        __syncthreads();

        {
            int kk = tid >> 2;
            int qs = (tid & 3) * 16;
            float cs = 0.0f;
#pragma unroll
            for (int tt = 0; tt < 16; ++tt) cs += Ps[(qs + tt)*PS_LD + kk];
            cs += __shfl_xor_sync(0xffffffffu, cs, 1);
            cs += __shfl_xor_sync(0xffffffffu, cs, 2);
            if ((tid & 3) == 0)
                atomicAdd(&atp[b * SS + k0 + kk], cs * INV_HS);
        }

#pragma unroll
        for (int kk = 0; kk < BKT; ++kk) {
            float vb[4];
            *(float4*)vb = *(const float4*)&Vs[kk*DK + tk];
            float pa[4];
#pragma unroll
            for (int i = 0; i < 4; ++i) pa[i] = Ps[(tq + i)*PS_LD + kk];
#pragma unroll
            for (int i = 0; i < 4; ++i)
#pragma unroll
                for (int j = 0; j < 4; ++j)
                    acc[i][j] = fmaf(pa[i], vb[j], acc[i][j]);
        }
    }

    float* Cg = g_C + ((size_t)(b * SS + q0)) * DD + h * DK;
#pragma unroll
    for (int i = 0; i < 4; ++i) {
        float4 o;
        o.x = acc[i][0]; o.y = acc[i][1]; o.z = acc[i][2]; o.w = acc[i][3];
        *(float4*)(Cg + (size_t)(tq + i) * DD + tk) = o;
    }
}

// ---------------- launch ------------------------------------------------------
extern "C" void kernel_launch(void* const* d_in, const int* in_sizes, int n_in,
                              void* d_out, int out_size) {
    (void)in_sizes; (void)n_in; (void)out_size;
    const float* query = (const float*)d_in[0];
    const float* key   = (const float*)d_in[1];
    const float* value = (const float*)d_in[2];
    const float* Wq = (const float*)d_in[3];
    const float* bq = (const float*)d_in[4];
    const float* Wk = (const float*)d_in[5];
    const float* bk = (const float*)d_in[6];
    const float* Wv = (const float*)d_in[7];
    const float* bv = (const float*)d_in[8];
    const float* Wo = (const float*)d_in[9];
    const float* bo = (const float*)d_in[10];

    float* out = (float*)d_out;
    float* atp = out + (size_t)BB * SS * DD;

    float *Qp, *Kp, *Vp, *Cp;
    cudaGetSymbolAddress((void**)&Qp, g_Q);
    cudaGetSymbolAddress((void**)&Kp, g_K);
    cudaGetSymbolAddress((void**)&Vp, g_V);
    cudaGetSymbolAddress((void**)&Cp, g_C);

    zero_atp_kernel<<<(BB*SS + 255) / 256, 256>>>(atp);

    cudaFuncSetAttribute(gemm_mma, cudaFuncAttributeMaxDynamicSharedMemorySize,
                         GEMM_SMEM);

    dim3 gg(GN / 128, MTOT / 128);
    gemm_mma<<<gg, 256, GEMM_SMEM>>>(query, Wq, bq, Qp);
    gemm_mma<<<gg, 256, GEMM_SMEM>>>(key,   Wk, bk, Kp);
    gemm_mma<<<gg, 256, GEMM_SMEM>>>(value, Wv, bv, Vp);

    static const size_t smem_bytes = SMEM_FLOATS * sizeof(float);
    cudaFuncSetAttribute(attn_kernel,
                         cudaFuncAttributeMaxDynamicSharedMemorySize,
                         (int)smem_bytes);
    attn_kernel<<<dim3(SS / BQ, BB * HH), 256, smem_bytes>>>(atp);

    gemm_mma<<<gg, 256, GEMM_SMEM>>>(Cp, Wo, bo, out);
}

// round 5
// speedup vs baseline: 1.1887x; 1.1887x over previous
#include <cuda_runtime.h>
#include <math.h>
#include <stdint.h>

#define BB 2
#define SS 2048
#define DD 1024
#define HH 16
#define DK 64
#define MTOT (BB*SS)

#define SCALE 12.5f                  // 100/sqrt(64)
#define INV_HS (1.0f/32768.0f)       // 1/(H*S)

// ---------------- scratch (static device globals; no allocation) -------------
__device__ float g_Q[MTOT*DD];
__device__ float g_K[MTOT*DD];
__device__ float g_V[MTOT*DD];
__device__ float g_C[MTOT*DD];
// score scratch: 512 blocks x 32 tiles x 256 threads x 32 floats = 512MB
__device__ float g_S[512ull * 32 * 256 * 32];

// ---------------- PTX helpers -------------------------------------------------
__device__ __forceinline__ uint32_t f32_to_tf32(float x) {
    uint32_t r;
    asm("cvt.rna.tf32.f32 %0, %1;" : "=r"(r) : "f"(x));
    return r;
}

__device__ __forceinline__ void split2(float v, float& hi, float& lo) {
    uint32_t h = f32_to_tf32(v);
    hi = __uint_as_float(h);
    lo = __uint_as_float(f32_to_tf32(v - hi));
}

__device__ __forceinline__ void mma_tf32(float c[4],
                                         uint32_t a0, uint32_t a1, uint32_t a2, uint32_t a3,
                                         uint32_t b0, uint32_t b1) {
    asm volatile(
        "mma.sync.aligned.m16n8k8.row.col.f32.tf32.tf32.f32 "
        "{%0,%1,%2,%3}, {%4,%5,%6,%7}, {%8,%9}, {%0,%1,%2,%3};"
        : "+f"(c[0]), "+f"(c[1]), "+f"(c[2]), "+f"(c[3])
        : "r"(a0), "r"(a1), "r"(a2), "r"(a3), "r"(b0), "r"(b1));
}

__device__ __forceinline__ uint32_t smem_u32(const void* p) {
    uint32_t a;
    asm("{ .reg .u64 t; cvta.to.shared.u64 t, %1; cvt.u32.u64 %0, t; }"
        : "=r"(a) : "l"(p));
    return a;
}

#define CP_ASYNC16(dst, src) \
    asm volatile("cp.async.cg.shared.global [%0], [%1], 16;" :: "r"(dst), "l"(src))
#define CP_COMMIT() asm volatile("cp.async.commit_group;" ::: "memory")
#define CP_WAIT1()  asm volatile("cp.async.wait_group 1;" ::: "memory")

// ---------------- zero mean_atp region ---------------------------------------
__global__ void zero_atp_kernel(float* __restrict__ atp) {
    int i = blockIdx.x * blockDim.x + threadIdx.x;
    if (i < BB*SS) atp[i] = 0.0f;
}

// ---------------- 3xTF32 mma.sync GEMM (unchanged from R3) --------------------
#define GK 1024
#define GN 1024
#define GBK 32
#define XS_LD 36
#define TILE_FLOATS (128 * XS_LD)
#define GEMM_SMEM (4 * TILE_FLOATS * 4)

__global__ __launch_bounds__(256) void gemm_mma(
    const float* __restrict__ X, const float* __restrict__ W,
    const float* __restrict__ bias, float* __restrict__ Y)
{
    extern __shared__ float sh[];
    float* Xs = sh;
    float* Ws = sh + 2 * TILE_FLOATS;

    const int t = threadIdx.x;
    const int w = t >> 5;
    const int lane = t & 31;
    const int g = lane >> 2;
    const int tig = lane & 3;
    const int warp_m = (w >> 2) * 64;
    const int warp_n = (w & 3) * 32;
    const int bm = blockIdx.y * 128;
    const int bn = blockIdx.x * 128;

    const int lrow = t >> 3;
    const int lcol = (t & 7) * 4;
    const uint32_t sbX = smem_u32(Xs);
    const uint32_t sbW = smem_u32(Ws);

    float acc[4][4][4];
#pragma unroll
    for (int mi = 0; mi < 4; ++mi)
#pragma unroll
        for (int ni = 0; ni < 4; ++ni)
#pragma unroll
            for (int j = 0; j < 4; ++j) acc[mi][ni][j] = 0.0f;

    const float* Xg = X + (size_t)(bm + lrow) * GK + lcol;
    const float* Wg = W + (size_t)(bn + lrow) * GK + lcol;

#pragma unroll
    for (int ir = 0; ir < 4; ++ir) {
        uint32_t dX = sbX + ((lrow + 32 * ir) * XS_LD + lcol) * 4;
        uint32_t dW = sbW + ((lrow + 32 * ir) * XS_LD + lcol) * 4;
        CP_ASYNC16(dX, Xg + (size_t)(32 * ir) * GK);
        CP_ASYNC16(dW, Wg + (size_t)(32 * ir) * GK);
    }
    CP_COMMIT();

    const int NSTAGE = GK / GBK;
    for (int s = 0; s < NSTAGE; ++s) {
        const int buf = s & 1;
        if (s + 1 < NSTAGE) {
            const int nbuf = (s + 1) & 1;
            const size_t ko = (size_t)(s + 1) * GBK;
#pragma unroll
            for (int ir = 0; ir < 4; ++ir) {
                uint32_t dX = sbX + (nbuf * TILE_FLOATS + (lrow + 32 * ir) * XS_LD + lcol) * 4;
                uint32_t dW = sbW + (nbuf * TILE_FLOATS + (lrow + 32 * ir) * XS_LD + lcol) * 4;
                CP_ASYNC16(dX, Xg + (size_t)(32 * ir) * GK + ko);
                CP_ASYNC16(dW, Wg + (size_t)(32 * ir) * GK + ko);
            }
        }
        CP_COMMIT();
        CP_WAIT1();
        __syncthreads();

        const float* xb = Xs + buf * TILE_FLOATS;
        const float* wb = Ws + buf * TILE_FLOATS;

#pragma unroll
        for (int k8 = 0; k8 < GBK / 8; ++k8) {
            const int k0 = k8 * 8;
            uint32_t AH[4][4], AL[4][4], BH[4][2], BL[4][2];
#pragma unroll
            for (int mi = 0; mi < 4; ++mi) {
                const int r0 = warp_m + mi * 16;
                float v0 = xb[(r0 + g) * XS_LD + k0 + tig];
                float v1 = xb[(r0 + g + 8) * XS_LD + k0 + tig];
                float v2 = xb[(r0 + g) * XS_LD + k0 + tig + 4];
                float v3 = xb[(r0 + g + 8) * XS_LD + k0 + tig + 4];
                AH[mi][0] = f32_to_tf32(v0); AL[mi][0] = f32_to_tf32(v0 - __uint_as_float(AH[mi][0]));
                AH[mi][1] = f32_to_tf32(v1); AL[mi][1] = f32_to_tf32(v1 - __uint_as_float(AH[mi][1]));
                AH[mi][2] = f32_to_tf32(v2); AL[mi][2] = f32_to_tf32(v2 - __uint_as_float(AH[mi][2]));
                AH[mi][3] = f32_to_tf32(v3); AL[mi][3] = f32_to_tf32(v3 - __uint_as_float(AH[mi][3]));
            }
#pragma unroll
            for (int ni = 0; ni < 4; ++ni) {
                const int r0 = warp_n + ni * 8;
                float v0 = wb[(r0 + g) * XS_LD + k0 + tig];
                float v1 = wb[(r0 + g) * XS_LD + k0 + tig + 4];
                BH[ni][0] = f32_to_tf32(v0); BL[ni][0] = f32_to_tf32(v0 - __uint_as_float(BH[ni][0]));
                BH[ni][1] = f32_to_tf32(v1); BL[ni][1] = f32_to_tf32(v1 - __uint_as_float(BH[ni][1]));
            }
#pragma unroll
            for (int mi = 0; mi < 4; ++mi)
#pragma unroll
                for (int ni = 0; ni < 4; ++ni) {
                    mma_tf32(acc[mi][ni], AH[mi][0], AH[mi][1], AH[mi][2], AH[mi][3],
                             BH[ni][0], BH[ni][1]);
                    mma_tf32(acc[mi][ni], AH[mi][0], AH[mi][1], AH[mi][2], AH[mi][3],
                             BL[ni][0], BL[ni][1]);
                    mma_tf32(acc[mi][ni], AL[mi][0], AL[mi][1], AL[mi][2], AL[mi][3],
                             BH[ni][0], BH[ni][1]);
                }
        }
        __syncthreads();
    }

#pragma unroll
    for (int ni = 0; ni < 4; ++ni) {
        const int n = bn + warp_n + ni * 8 + 2 * tig;
        const float2 b2 = *(const float2*)(bias + n);
#pragma unroll
        for (int mi = 0; mi < 4; ++mi) {
            const int r0 = bm + warp_m + mi * 16;
            float2 o0, o1;
            o0.x = acc[mi][ni][0] + b2.x; o0.y = acc[mi][ni][1] + b2.y;
            o1.x = acc[mi][ni][2] + b2.x; o1.y = acc[mi][ni][3] + b2.y;
            *(float2*)(Y + (size_t)(r0 + g) * GN + n)     = o0;
            *(float2*)(Y + (size_t)(r0 + g + 8) * GN + n) = o1;
        }
    }
}

// ---------------- tensor-core attention ---------------------------------------
// BQ=128 queries per block, BKT=64 keys per tile, 32 tiles, 8 warps (2m x 4n).
// Pass1: S = 12.5*Q*K^T via 3xTF32 mma -> thread-private global scratch +
//        per-thread online (m,l). Merge -> rowm / rowil.
// Pass2: read S, P=exp(s-m)*il (split hi/lo to smem), colsum->atp atomics,
//        O += P*V via 3xTF32 mma.
//
// smem float layout (union region 26112 floats):
//  pass1: QH@0(8704) QL@8704 KH@17408(4352) KL@21760
//  merge: mpart@0(512) lpart@512
//  pass2: PH@0(8704) PL@8704 VH@17408(4160) VL@21568
//  fixed: rowm@26112(128) rowil@26240(128)    total 26368 floats = 105472 B
#define AT_SMEM_FLOATS 26368
#define QK_LD 68
#define PS2_LD 68
#define VT_LD 65

__global__ __launch_bounds__(256, 2) void attn_mma(float* __restrict__ atp) {
    extern __shared__ float sh[];
    float* rowm  = sh + 26112;
    float* rowil = sh + 26240;

    const int t = threadIdx.x;
    const int w = t >> 5;
    const int lane = t & 31;
    const int g = lane >> 2;
    const int tig = lane & 3;
    const int wm = (w >> 2) * 64;        // query-row half
    const int wn = (w & 3) * 16;         // 16-col stripe (keys in p1, dk in p2)
    const int bh = blockIdx.y;
    const int b = bh >> 4, h = bh & 15;
    const int qt = blockIdx.x;
    const int q0 = qt * 128;

    const float* Qg = g_Q + ((size_t)(b * SS + q0)) * DD + h * DK;
    const float* Kg = g_K + ((size_t)(b * SS)) * DD + h * DK;
    const float* Vg = g_V + ((size_t)(b * SS)) * DD + h * DK;
    float* Sg = g_S + (((size_t)(bh * 16 + qt) * 32) * 256 + t) * 32;

    // ---- load Q 128x64, split into QH/QL ----
    float* QH = sh;
    float* QL = sh + 8704;
#pragma unroll
    for (int it = 0; it < 8; ++it) {
        int f4 = t + 256 * it;
        int row = f4 >> 4, c4 = f4 & 15;
        float4 v = *(const float4*)(Qg + (size_t)row * DD + c4 * 4);
        float h0,l0,h1,l1,h2,l2,h3,l3;
        split2(v.x,h0,l0); split2(v.y,h1,l1); split2(v.z,h2,l2); split2(v.w,h3,l3);
        int base = row * QK_LD + c4 * 4;
        *(float4*)&QH[base] = make_float4(h0,h1,h2,h3);
        *(float4*)&QL[base] = make_float4(l0,l1,l2,l3);
    }

    // ---- pass 1: scores + online (m,l) ----
    float* KH = sh + 17408;
    float* KL = sh + 21760;
    float m8[4][2], l8[4][2];
#pragma unroll
    for (int mi = 0; mi < 4; ++mi) {
        m8[mi][0] = -INFINITY; m8[mi][1] = -INFINITY;
        l8[mi][0] = 0.0f;      l8[mi][1] = 0.0f;
    }

    for (int tile = 0; tile < 32; ++tile) {
        __syncthreads();
#pragma unroll
        for (int it = 0; it < 4; ++it) {
            int f4 = t + 256 * it;
            int row = f4 >> 4, c4 = f4 & 15;
            float4 v = *(const float4*)(Kg + (size_t)(tile * 64 + row) * DD + c4 * 4);
            float h0,l0,h1,l1,h2,l2,h3,l3;
            split2(v.x,h0,l0); split2(v.y,h1,l1); split2(v.z,h2,l2); split2(v.w,h3,l3);
            int base = row * QK_LD + c4 * 4;
            *(float4*)&KH[base] = make_float4(h0,h1,h2,h3);
            *(float4*)&KL[base] = make_float4(l0,l1,l2,l3);
        }
        __syncthreads();

        float sacc[4][2][4];
#pragma unroll
        for (int mi = 0; mi < 4; ++mi)
#pragma unroll
            for (int ni = 0; ni < 2; ++ni)
#pragma unroll
                for (int j = 0; j < 4; ++j) sacc[mi][ni][j] = 0.0f;

#pragma unroll
        for (int k8 = 0; k8 < 8; ++k8) {
            const int k0 = k8 * 8;
            uint32_t ah[4][4], al[4][4], bhv[2][2], blv[2][2];
#pragma unroll
            for (int mi = 0; mi < 4; ++mi) {
                const int r0 = wm + mi * 16;
                ah[mi][0] = __float_as_uint(QH[(r0 + g)     * QK_LD + k0 + tig]);
                ah[mi][1] = __float_as_uint(QH[(r0 + g + 8) * QK_LD + k0 + tig]);
                ah[mi][2] = __float_as_uint(QH[(r0 + g)     * QK_LD + k0 + tig + 4]);
                ah[mi][3] = __float_as_uint(QH[(r0 + g + 8) * QK_LD + k0 + tig + 4]);
                al[mi][0] = __float_as_uint(QL[(r0 + g)     * QK_LD + k0 + tig]);
                al[mi][1] = __float_as_uint(QL[(r0 + g + 8) * QK_LD + k0 + tig]);
                al[mi][2] = __float_as_uint(QL[(r0 + g)     * QK_LD + k0 + tig + 4]);
                al[mi][3] = __float_as_uint(QL[(r0 + g + 8) * QK_LD + k0 + tig + 4]);
            }
#pragma unroll
            for (int ni = 0; ni < 2; ++ni) {
                const int key = wn + ni * 8 + g;
                bhv[ni][0] = __float_as_uint(KH[key * QK_LD + k0 + tig]);
                bhv[ni][1] = __float_as_uint(KH[key * QK_LD + k0 + tig + 4]);
                blv[ni][0] = __float_as_uint(KL[key * QK_LD + k0 + tig]);
                blv[ni][1] = __float_as_uint(KL[key * QK_LD + k0 + tig + 4]);
            }
#pragma unroll
            for (int mi = 0; mi < 4; ++mi)
#pragma unroll
                for (int ni = 0; ni < 2; ++ni) {
                    mma_tf32(sacc[mi][ni], ah[mi][0], ah[mi][1], ah[mi][2], ah[mi][3],
                             bhv[ni][0], bhv[ni][1]);
                    mma_tf32(sacc[mi][ni], ah[mi][0], ah[mi][1], ah[mi][2], ah[mi][3],
                             blv[ni][0], blv[ni][1]);
                    mma_tf32(sacc[mi][ni], al[mi][0], al[mi][1], al[mi][2], al[mi][3],
                             bhv[ni][0], bhv[ni][1]);
                }
        }

        // scale, store to scratch, online update
        float* Sp = Sg + (size_t)tile * 8192;
#pragma unroll
        for (int mi = 0; mi < 4; ++mi) {
#pragma unroll
            for (int ni = 0; ni < 2; ++ni) {
#pragma unroll
                for (int j = 0; j < 4; ++j) sacc[mi][ni][j] *= SCALE;
                *(float4*)(Sp + (mi * 2 + ni) * 4) =
                    make_float4(sacc[mi][ni][0], sacc[mi][ni][1],
                                sacc[mi][ni][2], sacc[mi][ni][3]);
            }
#pragma unroll
            for (int r = 0; r < 2; ++r) {
                float v0 = sacc[mi][0][r*2], v1 = sacc[mi][0][r*2+1];
                float v2 = sacc[mi][1][r*2], v3 = sacc[mi][1][r*2+1];
                float mx = fmaxf(fmaxf(v0, v1), fmaxf(v2, v3));
                float mo = m8[mi][r];
                float mn = fmaxf(mo, mx);
                l8[mi][r] = l8[mi][r] * __expf(mo - mn)
                          + __expf(v0 - mn) + __expf(v1 - mn)
                          + __expf(v2 - mn) + __expf(v3 - mn);
                m8[mi][r] = mn;
            }
        }
    }

    // ---- merge (m,l): across tig, then across the 4 n-stripe warps ----
    __syncthreads();   // pass1 smem reads done; safe to overlay mpart/lpart
    float* mpart = sh;
    float* lpart = sh + 512;
#pragma unroll
    for (int mi = 0; mi < 4; ++mi)
#pragma unroll
        for (int r = 0; r < 2; ++r) {
            float m = m8[mi][r], l = l8[mi][r];
#pragma unroll
            for (int off = 1; off <= 2; off <<= 1) {
                float mo = __shfl_xor_sync(0xffffffffu, m, off);
                float lo = __shfl_xor_sync(0xffffffffu, l, off);
                float mn = fmaxf(m, mo);
                l = l * __expf(m - mn) + lo * __expf(mo - mn);
                m = mn;
            }
            if (tig == 0) {
                int row = wm + mi * 16 + g + r * 8;
                mpart[(w & 3) * 128 + row] = m;
                lpart[(w & 3) * 128 + row] = l;
            }
        }
    __syncthreads();
    if (t < 128) {
        float m = mpart[t], l = lpart[t];
#pragma unroll
        for (int p = 1; p < 4; ++p) {
            float mo = mpart[p * 128 + t], lo = lpart[p * 128 + t];
            float mn = fmaxf(m, mo);
            l = l * __expf(m - mn) + lo * __expf(mo - mn);
            m = mn;
        }
        rowm[t] = m;
        rowil[t] = 1.0f / l;
    }
    __syncthreads();

    // ---- pass 2 ----
    float* PH = sh;
    float* PL = sh + 8704;
    float* VH = sh + 17408;
    float* VL = sh + 21568;

    float my_m[4][2], my_il[4][2];
#pragma unroll
    for (int mi = 0; mi < 4; ++mi)
#pragma unroll
        for (int r = 0; r < 2; ++r) {
            int row = wm + mi * 16 + g + r * 8;
            my_m[mi][r] = rowm[row];
            my_il[mi][r] = rowil[row];
        }

    float oacc[4][2][4];
#pragma unroll
    for (int mi = 0; mi < 4; ++mi)
#pragma unroll
        for (int ni = 0; ni < 2; ++ni)
#pragma unroll
            for (int j = 0; j < 4; ++j) oacc[mi][ni][j] = 0.0f;

    for (int tile = 0; tile < 32; ++tile) {
        __syncthreads();
        // V tile load + transpose + split
#pragma unroll
        for (int it = 0; it < 4; ++it) {
            int f4 = t + 256 * it;
            int row = f4 >> 4, c4 = f4 & 15;
            float4 v = *(const float4*)(Vg + (size_t)(tile * 64 + row) * DD + c4 * 4);
            float h0,l0,h1,l1,h2,l2,h3,l3;
            split2(v.x,h0,l0); split2(v.y,h1,l1); split2(v.z,h2,l2); split2(v.w,h3,l3);
            VH[(c4*4 + 0) * VT_LD + row] = h0; VL[(c4*4 + 0) * VT_LD + row] = l0;
            VH[(c4*4 + 1) * VT_LD + row] = h1; VL[(c4*4 + 1) * VT_LD + row] = l1;
            VH[(c4*4 + 2) * VT_LD + row] = h2; VL[(c4*4 + 2) * VT_LD + row] = l2;
            VH[(c4*4 + 3) * VT_LD + row] = h3; VL[(c4*4 + 3) * VT_LD + row] = l3;
        }
        // S -> P (split) -> smem
        const float* Sp = Sg + (size_t)tile * 8192;
#pragma unroll
        for (int mi = 0; mi < 4; ++mi)
#pragma unroll
            for (int ni = 0; ni < 2; ++ni) {
                float4 s4 = *(const float4*)(Sp + (mi * 2 + ni) * 4);
                float p0 = __expf(s4.x - my_m[mi][0]) * my_il[mi][0];
                float p1 = __expf(s4.y - my_m[mi][0]) * my_il[mi][0];
                float p2 = __expf(s4.z - my_m[mi][1]) * my_il[mi][1];
                float p3 = __expf(s4.w - my_m[mi][1]) * my_il[mi][1];
                float h0,l0,h1,l1,h2,l2,h3,l3;
                split2(p0,h0,l0); split2(p1,h1,l1); split2(p2,h2,l2); split2(p3,h3,l3);
                int col = wn + ni * 8 + 2 * tig;
                int r0 = wm + mi * 16 + g;
                *(float2*)&PH[r0 * PS2_LD + col]       = make_float2(h0, h1);
                *(float2*)&PL[r0 * PS2_LD + col]       = make_float2(l0, l1);
                *(float2*)&PH[(r0 + 8) * PS2_LD + col] = make_float2(h2, h3);
                *(float2*)&PL[(r0 + 8) * PS2_LD + col] = make_float2(l2, l3);
            }
        __syncthreads();

        // column sums -> atp
        {
            int kk = t & 63;
            int part = t >> 6;
            float cs = 0.0f;
#pragma unroll
            for (int r = 0; r < 32; ++r) {
                int row = part * 32 + r;
                cs += PH[row * PS2_LD + kk] + PL[row * PS2_LD + kk];
            }
            atomicAdd(&atp[b * SS + tile * 64 + kk], cs * INV_HS);
        }

        // PV mma
#pragma unroll
        for (int k8 = 0; k8 < 8; ++k8) {
            const int k0 = k8 * 8;
            uint32_t ah[4][4], al[4][4], bhv[2][2], blv[2][2];
#pragma unroll
            for (int mi = 0; mi < 4; ++mi) {
                const int r0 = wm + mi * 16;
                ah[mi][0] = __float_as_uint(PH[(r0 + g)     * PS2_LD + k0 + tig]);
                ah[mi][1] = __float_as_uint(PH[(r0 + g + 8) * PS2_LD + k0 + tig]);
                ah[mi][2] = __float_as_uint(PH[(r0 + g)     * PS2_LD + k0 + tig + 4]);
                ah[mi][3] = __float_as_uint(PH[(r0 + g + 8) * PS2_LD + k0 + tig + 4]);
                al[mi][0] = __float_as_uint(PL[(r0 + g)     * PS2_LD + k0 + tig]);
                al[mi][1] = __float_as_uint(PL[(r0 + g + 8) * PS2_LD + k0 + tig]);
                al[mi][2] = __float_as_uint(PL[(r0 + g)     * PS2_LD + k0 + tig + 4]);
                al[mi][3] = __float_as_uint(PL[(r0 + g + 8) * PS2_LD + k0 + tig + 4]);
            }
#pragma unroll
            for (int ni = 0; ni < 2; ++ni) {
                const int dk = wn + ni * 8 + g;
                bhv[ni][0] = __float_as_uint(VH[dk * VT_LD + k0 + tig]);
                bhv[ni][1] = __float_as_uint(VH[dk * VT_LD + k0 + tig + 4]);
                blv[ni][0] = __float_as_uint(VL[dk * VT_LD + k0 + tig]);
                blv[ni][1] = __float_as_uint(VL[dk * VT_LD + k0 + tig + 4]);
            }
#pragma unroll
            for (int mi = 0; mi < 4; ++mi)
#pragma unroll
                for (int ni = 0; ni < 2; ++ni) {
                    mma_tf32(oacc[mi][ni], ah[mi][0], ah[mi][1], ah[mi][2], ah[mi][3],
                             bhv[ni][0], bhv[ni][1]);
                    mma_tf32(oacc[mi][ni], ah[mi][0], ah[mi][1], ah[mi][2], ah[mi][3],
                             blv[ni][0], blv[ni][1]);
                    mma_tf32(oacc[mi][ni], al[mi][0], al[mi][1], al[mi][2], al[mi][3],
                             bhv[ni][0], bhv[ni][1]);
                }
        }
    }

    // ---- epilogue: write context ----
    float* Cg = g_C + ((size_t)(b * SS + q0)) * DD + h * DK;
#pragma unroll
    for (int mi = 0; mi < 4; ++mi)
#pragma unroll
        for (int ni = 0; ni < 2; ++ni) {
            const int col = wn + ni * 8 + 2 * tig;
            const int r0 = wm + mi * 16 + g;
            *(float2*)(Cg + (size_t)r0 * DD + col) =
                make_float2(oacc[mi][ni][0], oacc[mi][ni][1]);
            *(float2*)(Cg + (size_t)(r0 + 8) * DD + col) =
                make_float2(oacc[mi][ni][2], oacc[mi][ni][3]);
        }
}

// ---------------- launch ------------------------------------------------------
extern "C" void kernel_launch(void* const* d_in, const int* in_sizes, int n_in,
                              void* d_out, int out_size) {
    (void)in_sizes; (void)n_in; (void)out_size;
    const float* query = (const float*)d_in[0];
    const float* key   = (const float*)d_in[1];
    const float* value = (const float*)d_in[2];
    const float* Wq = (const float*)d_in[3];
    const float* bq = (const float*)d_in[4];
    const float* Wk = (const float*)d_in[5];
    const float* bk = (const float*)d_in[6];
    const float* Wv = (const float*)d_in[7];
    const float* bv = (const float*)d_in[8];
    const float* Wo = (const float*)d_in[9];
    const float* bo = (const float*)d_in[10];

    float* out = (float*)d_out;
    float* atp = out + (size_t)BB * SS * DD;

    float *Qp, *Kp, *Vp, *Cp;
    cudaGetSymbolAddress((void**)&Qp, g_Q);
    cudaGetSymbolAddress((void**)&Kp, g_K);
    cudaGetSymbolAddress((void**)&Vp, g_V);
    cudaGetSymbolAddress((void**)&Cp, g_C);

    zero_atp_kernel<<<(BB*SS + 255) / 256, 256>>>(atp);

    cudaFuncSetAttribute(gemm_mma, cudaFuncAttributeMaxDynamicSharedMemorySize,
                         GEMM_SMEM);

    dim3 gg(GN / 128, MTOT / 128);
    gemm_mma<<<gg, 256, GEMM_SMEM>>>(query, Wq, bq, Qp);
    gemm_mma<<<gg, 256, GEMM_SMEM>>>(key,   Wk, bk, Kp);
    gemm_mma<<<gg, 256, GEMM_SMEM>>>(value, Wv, bv, Vp);

    const int at_smem = AT_SMEM_FLOATS * 4;
    cudaFuncSetAttribute(attn_mma, cudaFuncAttributeMaxDynamicSharedMemorySize,
                         at_smem);
    attn_mma<<<dim3(16, 32), 256, at_smem>>>(atp);

    gemm_mma<<<gg, 256, GEMM_SMEM>>>(Cp, Wo, bo, out);
}

// round 6
// speedup vs baseline: 1.8617x; 1.5662x over previous
#include <cuda_runtime.h>
#include <cuda_fp16.h>
#include <math.h>
#include <stdint.h>

#define BB 2
#define SS 2048
#define DD 1024
#define HH 16
#define DK 64
#define MTOT (BB*SS)

#define SCALE 12.5f                  // 100/sqrt(64)
#define INV_HS (1.0f/32768.0f)       // 1/(H*S)

// ---------------- scratch (static device globals; no allocation) -------------
__device__ float g_Q[MTOT*DD];
__device__ float g_K[MTOT*DD];
__device__ float g_V[MTOT*DD];
__device__ float g_C[MTOT*DD];
// score scratch: 512 blocks x 32 tiles x 256 threads x 32 floats = 512MB
__device__ float g_S[512ull * 32 * 256 * 32];

// ---------------- helpers -----------------------------------------------------
__device__ __forceinline__ void split_h2(float a, float b, __half2& h, __half2& l) {
    h = __floats2half2_rn(a, b);
    float2 f = __half22float2(h);
    l = __floats2half2_rn(a - f.x, b - f.y);
}

__device__ __forceinline__ void mma_f16(float c[4],
                                        uint32_t a0, uint32_t a1, uint32_t a2, uint32_t a3,
                                        uint32_t b0, uint32_t b1) {
    asm volatile(
        "mma.sync.aligned.m16n8k16.row.col.f32.f16.f16.f32 "
        "{%0,%1,%2,%3}, {%4,%5,%6,%7}, {%8,%9}, {%0,%1,%2,%3};"
        : "+f"(c[0]), "+f"(c[1]), "+f"(c[2]), "+f"(c[3])
        : "r"(a0), "r"(a1), "r"(a2), "r"(a3), "r"(b0), "r"(b1));
}

#define U32AT(p) (*(const uint32_t*)(p))

// ---------------- zero mean_atp region ---------------------------------------
__global__ void zero_atp_kernel(float* __restrict__ atp) {
    int i = blockIdx.x * blockDim.x + threadIdx.x;
    if (i < BB*SS) atp[i] = 0.0f;
}

// ---------------- 3xFP16 mma.sync GEMM: Y[M,1024] = X @ W^T + b ---------------
// BM=BN=128, BK=32, 256 threads (8 warps 2x4), warp tile 64x32, m16n8k16.
#define GK 1024
#define GN 1024
#define LDH 40                         // halfs per smem row (32 + 8 pad)
#define GEMM_SMEM 40960                // XsH,XsL,WsH,WsL: 4 * 128*40*2 bytes

__global__ __launch_bounds__(256, 2) void gemm_h(
    const float* __restrict__ X, const float* __restrict__ W,
    const float* __restrict__ bias, float* __restrict__ Y)
{
    extern __shared__ char sm[];
    __half* XsH = (__half*)sm;                     // [128][40]
    __half* XsL = (__half*)(sm + 10240);
    __half* WsH = (__half*)(sm + 20480);
    __half* WsL = (__half*)(sm + 30720);

    const int t = threadIdx.x;
    const int w = t >> 5;
    const int lane = t & 31;
    const int g = lane >> 2;
    const int tig = lane & 3;
    const int warp_m = (w >> 2) * 64;
    const int warp_n = (w & 3) * 32;
    const int bm = blockIdx.y * 128;
    const int bn = blockIdx.x * 128;

    const int lrow = t >> 3;              // 0..31
    const int lcol = (t & 7) * 4;         // 0..28

    float acc[4][4][4];
#pragma unroll
    for (int mi = 0; mi < 4; ++mi)
#pragma unroll
        for (int ni = 0; ni < 4; ++ni)
#pragma unroll
            for (int j = 0; j < 4; ++j) acc[mi][ni][j] = 0.0f;

    const float* Xg = X + (size_t)(bm + lrow) * GK + lcol;
    const float* Wg = W + (size_t)(bn + lrow) * GK + lcol;

    for (int s = 0; s < GK / 32; ++s) {
        __syncthreads();
#pragma unroll
        for (int ir = 0; ir < 4; ++ir) {
            const int row = lrow + 32 * ir;
            float4 xv = *(const float4*)(Xg + (size_t)(32 * ir) * GK + s * 32);
            float4 wv = *(const float4*)(Wg + (size_t)(32 * ir) * GK + s * 32);
            __half2 h01, l01, h23, l23;
            split_h2(xv.x, xv.y, h01, l01);
            split_h2(xv.z, xv.w, h23, l23);
            *(__half2*)&XsH[row * LDH + lcol]     = h01;
            *(__half2*)&XsH[row * LDH + lcol + 2] = h23;
            *(__half2*)&XsL[row * LDH + lcol]     = l01;
            *(__half2*)&XsL[row * LDH + lcol + 2] = l23;
            split_h2(wv.x, wv.y, h01, l01);
            split_h2(wv.z, wv.w, h23, l23);
            *(__half2*)&WsH[row * LDH + lcol]     = h01;
            *(__half2*)&WsH[row * LDH + lcol + 2] = h23;
            *(__half2*)&WsL[row * LDH + lcol]     = l01;
            *(__half2*)&WsL[row * LDH + lcol + 2] = l23;
        }
        __syncthreads();

#pragma unroll
        for (int k16 = 0; k16 < 2; ++k16) {
            const int k0 = k16 * 16;
            uint32_t bh[4][2], bl[4][2];
#pragma unroll
            for (int ni = 0; ni < 4; ++ni) {
                const int r = warp_n + ni * 8 + g;
                bh[ni][0] = U32AT(&WsH[r * LDH + k0 + 2 * tig]);
                bh[ni][1] = U32AT(&WsH[r * LDH + k0 + 8 + 2 * tig]);
                bl[ni][0] = U32AT(&WsL[r * LDH + k0 + 2 * tig]);
                bl[ni][1] = U32AT(&WsL[r * LDH + k0 + 8 + 2 * tig]);
            }
#pragma unroll
            for (int mi = 0; mi < 4; ++mi) {
                const int r0 = warp_m + mi * 16;
                uint32_t ah[4], al[4];
                ah[0] = U32AT(&XsH[(r0 + g)     * LDH + k0 + 2 * tig]);
                ah[1] = U32AT(&XsH[(r0 + g + 8) * LDH + k0 + 2 * tig]);
                ah[2] = U32AT(&XsH[(r0 + g)     * LDH + k0 + 8 + 2 * tig]);
                ah[3] = U32AT(&XsH[(r0 + g + 8) * LDH + k0 + 8 + 2 * tig]);
                al[0] = U32AT(&XsL[(r0 + g)     * LDH + k0 + 2 * tig]);
                al[1] = U32AT(&XsL[(r0 + g + 8) * LDH + k0 + 2 * tig]);
                al[2] = U32AT(&XsL[(r0 + g)     * LDH + k0 + 8 + 2 * tig]);
                al[3] = U32AT(&XsL[(r0 + g + 8) * LDH + k0 + 8 + 2 * tig]);
#pragma unroll
                for (int ni = 0; ni < 4; ++ni) {
                    mma_f16(acc[mi][ni], ah[0], ah[1], ah[2], ah[3], bh[ni][0], bh[ni][1]);
                    mma_f16(acc[mi][ni], ah[0], ah[1], ah[2], ah[3], bl[ni][0], bl[ni][1]);
                    mma_f16(acc[mi][ni], al[0], al[1], al[2], al[3], bh[ni][0], bh[ni][1]);
                }
            }
        }
    }

    // epilogue: write with bias
#pragma unroll
    for (int ni = 0; ni < 4; ++ni) {
        const int n = bn + warp_n + ni * 8 + 2 * tig;
        const float2 b2 = *(const float2*)(bias + n);
#pragma unroll
        for (int mi = 0; mi < 4; ++mi) {
            const int r0 = bm + warp_m + mi * 16;
            float2 o0, o1;
            o0.x = acc[mi][ni][0] + b2.x; o0.y = acc[mi][ni][1] + b2.y;
            o1.x = acc[mi][ni][2] + b2.x; o1.y = acc[mi][ni][3] + b2.y;
            *(float2*)(Y + (size_t)(r0 + g) * GN + n)     = o0;
            *(float2*)(Y + (size_t)(r0 + g + 8) * GN + n) = o1;
        }
    }
}

// ---------------- 3xFP16 tensor-core attention --------------------------------
// BQ=128 per block, BKT=64 per tile, 32 tiles, 8 warps (2m x 4n), m16n8k16.
// smem bytes: QH@0[128][72] QL@18432 | KH@36864[64][72] KL@46080
//             pass2: PH=QH PL=QL VH=KH VL=KL (V transposed: [dk][key])
//             rowm@55296(128f) rowil@55808(128f)   total 56320 B
#define AT_SMEM 56320
#define ALD 72

__global__ __launch_bounds__(256, 2) void attn_mma(float* __restrict__ atp) {
    extern __shared__ char sm[];
    __half* QH = (__half*)sm;
    __half* QL = (__half*)(sm + 18432);
    __half* KH = (__half*)(sm + 36864);
    __half* KL = (__half*)(sm + 46080);
    __half* PH = QH;
    __half* PL = QL;
    __half* VH = KH;
    __half* VL = KL;
    float* rowm  = (float*)(sm + 55296);
    float* rowil = (float*)(sm + 55808);
    float* mpart = (float*)sm;             // merge overlay (512 f)
    float* lpart = (float*)(sm + 2048);    // (512 f)

    const int t = threadIdx.x;
    const int w = t >> 5;
    const int lane = t & 31;
    const int g = lane >> 2;
    const int tig = lane & 3;
    const int wm = (w >> 2) * 64;
    const int wn = (w & 3) * 16;
    const int bh = blockIdx.y;
    const int b = bh >> 4, h = bh & 15;
    const int qt = blockIdx.x;
    const int q0 = qt * 128;

    const float* Qg = g_Q + ((size_t)(b * SS + q0)) * DD + h * DK;
    const float* Kg = g_K + ((size_t)(b * SS)) * DD + h * DK;
    const float* Vg = g_V + ((size_t)(b * SS)) * DD + h * DK;
    float* Sg = g_S + (((size_t)(bh * 16 + qt) * 32) * 256 + t) * 32;

    // ---- load Q 128x64 -> QH/QL ----
#pragma unroll
    for (int it = 0; it < 8; ++it) {
        int f4 = t + 256 * it;
        int row = f4 >> 4, c4 = f4 & 15;
        float4 v = *(const float4*)(Qg + (size_t)row * DD + c4 * 4);
        __half2 h01, l01, h23, l23;
        split_h2(v.x, v.y, h01, l01);
        split_h2(v.z, v.w, h23, l23);
        int base = row * ALD + c4 * 4;
        *(__half2*)&QH[base]     = h01;
        *(__half2*)&QH[base + 2] = h23;
        *(__half2*)&QL[base]     = l01;
        *(__half2*)&QL[base + 2] = l23;
    }

    // ---- pass 1: scores + online (m,l) ----
    float m8[4][2], l8[4][2];
#pragma unroll
    for (int mi = 0; mi < 4; ++mi) {
        m8[mi][0] = -INFINITY; m8[mi][1] = -INFINITY;
        l8[mi][0] = 0.0f;      l8[mi][1] = 0.0f;
    }

    for (int tile = 0; tile < 32; ++tile) {
        __syncthreads();
#pragma unroll
        for (int it = 0; it < 4; ++it) {
            int f4 = t + 256 * it;
            int row = f4 >> 4, c4 = f4 & 15;
            float4 v = *(const float4*)(Kg + (size_t)(tile * 64 + row) * DD + c4 * 4);
            __half2 h01, l01, h23, l23;
            split_h2(v.x, v.y, h01, l01);
            split_h2(v.z, v.w, h23, l23);
            int base = row * ALD + c4 * 4;
            *(__half2*)&KH[base]     = h01;
            *(__half2*)&KH[base + 2] = h23;
            *(__half2*)&KL[base]     = l01;
            *(__half2*)&KL[base + 2] = l23;
        }
        __syncthreads();

        float sacc[4][2][4];
#pragma unroll
        for (int mi = 0; mi < 4; ++mi)
#pragma unroll
            for (int ni = 0; ni < 2; ++ni)
#pragma unroll
                for (int j = 0; j < 4; ++j) sacc[mi][ni][j] = 0.0f;

#pragma unroll
        for (int k16 = 0; k16 < 4; ++k16) {
            const int k0 = k16 * 16;
            uint32_t bhv[2][2], blv[2][2];
#pragma unroll
            for (int ni = 0; ni < 2; ++ni) {
                const int key = wn + ni * 8 + g;
                bhv[ni][0] = U32AT(&KH[key * ALD + k0 + 2 * tig]);
                bhv[ni][1] = U32AT(&KH[key * ALD + k0 + 8 + 2 * tig]);
                blv[ni][0] = U32AT(&KL[key * ALD + k0 + 2 * tig]);
                blv[ni][1] = U32AT(&KL[key * ALD + k0 + 8 + 2 * tig]);
            }
#pragma unroll
            for (int mi = 0; mi < 4; ++mi) {
                const int r0 = wm + mi * 16;
                uint32_t ah[4], al[4];
                ah[0] = U32AT(&QH[(r0 + g)     * ALD + k0 + 2 * tig]);
                ah[1] = U32AT(&QH[(r0 + g + 8) * ALD + k0 + 2 * tig]);
                ah[2] = U32AT(&QH[(r0 + g)     * ALD + k0 + 8 + 2 * tig]);
                ah[3] = U32AT(&QH[(r0 + g + 8) * ALD + k0 + 8 + 2 * tig]);
                al[0] = U32AT(&QL[(r0 + g)     * ALD + k0 + 2 * tig]);
                al[1] = U32AT(&QL[(r0 + g + 8) * ALD + k0 + 2 * tig]);
                al[2] = U32AT(&QL[(r0 + g)     * ALD + k0 + 8 + 2 * tig]);
                al[3] = U32AT(&QL[(r0 + g + 8) * ALD + k0 + 8 + 2 * tig]);
#pragma unroll
                for (int ni = 0; ni < 2; ++ni) {
                    mma_f16(sacc[mi][ni], ah[0], ah[1], ah[2], ah[3], bhv[ni][0], bhv[ni][1]);
                    mma_f16(sacc[mi][ni], ah[0], ah[1], ah[2], ah[3], blv[ni][0], blv[ni][1]);
                    mma_f16(sacc[mi][ni], al[0], al[1], al[2], al[3], bhv[ni][0], bhv[ni][1]);
                }
            }
        }

        // scale, store to scratch, online update
        float* Sp = Sg + (size_t)tile * 8192;
#pragma unroll
        for (int mi = 0; mi < 4; ++mi) {
#pragma unroll
            for (int ni = 0; ni < 2; ++ni) {
#pragma unroll
                for (int j = 0; j < 4; ++j) sacc[mi][ni][j] *= SCALE;
                *(float4*)(Sp + (mi * 2 + ni) * 4) =
                    make_float4(sacc[mi][ni][0], sacc[mi][ni][1],
                                sacc[mi][ni][2], sacc[mi][ni][3]);
            }
#pragma unroll
            for (int r = 0; r < 2; ++r) {
                float v0 = sacc[mi][0][r*2], v1 = sacc[mi][0][r*2+1];
                float v2 = sacc[mi][1][r*2], v3 = sacc[mi][1][r*2+1];
                float mx = fmaxf(fmaxf(v0, v1), fmaxf(v2, v3));
                float mo = m8[mi][r];
                float mn = fmaxf(mo, mx);
                l8[mi][r] = l8[mi][r] * __expf(mo - mn)
                          + __expf(v0 - mn) + __expf(v1 - mn)
                          + __expf(v2 - mn) + __expf(v3 - mn);
                m8[mi][r] = mn;
            }
        }
    }

    // ---- merge (m,l) ----
    __syncthreads();
#pragma unroll
    for (int mi = 0; mi < 4; ++mi)
#pragma unroll
        for (int r = 0; r < 2; ++r) {
            float m = m8[mi][r], l = l8[mi][r];
#pragma unroll
            for (int off = 1; off <= 2; off <<= 1) {
                float mo = __shfl_xor_sync(0xffffffffu, m, off);
                float lo = __shfl_xor_sync(0xffffffffu, l, off);
                float mn = fmaxf(m, mo);
                l = l * __expf(m - mn) + lo * __expf(mo - mn);
                m = mn;
            }
            if (tig == 0) {
                int row = wm + mi * 16 + g + r * 8;
                mpart[(w & 3) * 128 + row] = m;
                lpart[(w & 3) * 128 + row] = l;
            }
        }
    __syncthreads();
    if (t < 128) {
        float m = mpart[t], l = lpart[t];
#pragma unroll
        for (int p = 1; p < 4; ++p) {
            float mo = mpart[p * 128 + t], lo = lpart[p * 128 + t];
            float mn = fmaxf(m, mo);
            l = l * __expf(m - mn) + lo * __expf(mo - mn);
            m = mn;
        }
        rowm[t] = m;
        rowil[t] = 1.0f / l;
    }
    __syncthreads();

    // ---- pass 2 ----
    float my_m[4][2], my_il[4][2];
#pragma unroll
    for (int mi = 0; mi < 4; ++mi)
#pragma unroll
        for (int r = 0; r < 2; ++r) {
            int row = wm + mi * 16 + g + r * 8;
            my_m[mi][r] = rowm[row];
            my_il[mi][r] = rowil[row];
        }

    float oacc[4][2][4];
#pragma unroll
    for (int mi = 0; mi < 4; ++mi)
#pragma unroll
        for (int ni = 0; ni < 2; ++ni)
#pragma unroll
            for (int j = 0; j < 4; ++j) oacc[mi][ni][j] = 0.0f;

    for (int tile = 0; tile < 32; ++tile) {
        __syncthreads();
        // V tile load + transpose + split: VH/VL [dk][key]
#pragma unroll
        for (int it = 0; it < 4; ++it) {
            int f4 = t + 256 * it;
            int row = f4 >> 4, c4 = f4 & 15;
            float4 v = *(const float4*)(Vg + (size_t)(tile * 64 + row) * DD + c4 * 4);
            float vv[4] = {v.x, v.y, v.z, v.w};
#pragma unroll
            for (int j = 0; j < 4; ++j) {
                __half hh = __float2half_rn(vv[j]);
                __half ll = __float2half_rn(vv[j] - __half2float(hh));
                VH[(c4 * 4 + j) * ALD + row] = hh;
                VL[(c4 * 4 + j) * ALD + row] = ll;
            }
        }

        // S -> P (exact fp32) -> colsum regs + split to PH/PL
        const float* Sp = Sg + (size_t)tile * 8192;
        float csum[2][2] = {{0.f, 0.f}, {0.f, 0.f}};
#pragma unroll
        for (int mi = 0; mi < 4; ++mi)
#pragma unroll
            for (int ni = 0; ni < 2; ++ni) {
                float4 s4 = *(const float4*)(Sp + (mi * 2 + ni) * 4);
                float p0 = __expf(s4.x - my_m[mi][0]) * my_il[mi][0];
                float p1 = __expf(s4.y - my_m[mi][0]) * my_il[mi][0];
                float p2 = __expf(s4.z - my_m[mi][1]) * my_il[mi][1];
                float p3 = __expf(s4.w - my_m[mi][1]) * my_il[mi][1];
                csum[ni][0] += p0 + p2;
                csum[ni][1] += p1 + p3;
                __half2 hA, lA, hB, lB;
                split_h2(p0, p1, hA, lA);
                split_h2(p2, p3, hB, lB);
                int col = wn + ni * 8 + 2 * tig;
                int r0 = wm + mi * 16 + g;
                *(__half2*)&PH[r0 * ALD + col]       = hA;
                *(__half2*)&PL[r0 * ALD + col]       = lA;
                *(__half2*)&PH[(r0 + 8) * ALD + col] = hB;
                *(__half2*)&PL[(r0 + 8) * ALD + col] = lB;
            }

        // colsum reduce over g lanes, atomicAdd
#pragma unroll
        for (int ni = 0; ni < 2; ++ni)
#pragma unroll
            for (int c = 0; c < 2; ++c) {
                float v = csum[ni][c];
                v += __shfl_xor_sync(0xffffffffu, v, 4);
                v += __shfl_xor_sync(0xffffffffu, v, 8);
                v += __shfl_xor_sync(0xffffffffu, v, 16);
                if (lane < 4)
                    atomicAdd(&atp[b * SS + tile * 64 + wn + ni * 8 + 2 * tig + c],
                              v * INV_HS);
            }
        __syncthreads();

        // PV mma: A = P, B = V^T
#pragma unroll
        for (int k16 = 0; k16 < 4; ++k16) {
            const int k0 = k16 * 16;
            uint32_t bhv[2][2], blv[2][2];
#pragma unroll
            for (int ni = 0; ni < 2; ++ni) {
                const int dk = wn + ni * 8 + g;
                bhv[ni][0] = U32AT(&VH[dk * ALD + k0 + 2 * tig]);
                bhv[ni][1] = U32AT(&VH[dk * ALD + k0 + 8 + 2 * tig]);
                blv[ni][0] = U32AT(&VL[dk * ALD + k0 + 2 * tig]);
                blv[ni][1] = U32AT(&VL[dk * ALD + k0 + 8 + 2 * tig]);
            }
#pragma unroll
            for (int mi = 0; mi < 4; ++mi) {
                const int r0 = wm + mi * 16;
                uint32_t ah[4], al[4];
                ah[0] = U32AT(&PH[(r0 + g)     * ALD + k0 + 2 * tig]);
                ah[1] = U32AT(&PH[(r0 + g + 8) * ALD + k0 + 2 * tig]);
                ah[2] = U32AT(&PH[(r0 + g)     * ALD + k0 + 8 + 2 * tig]);
                ah[3] = U32AT(&PH[(r0 + g + 8) * ALD + k0 + 8 + 2 * tig]);
                al[0] = U32AT(&PL[(r0 + g)     * ALD + k0 + 2 * tig]);
                al[1] = U32AT(&PL[(r0 + g + 8) * ALD + k0 + 2 * tig]);
                al[2] = U32AT(&PL[(r0 + g)     * ALD + k0 + 8 + 2 * tig]);
                al[3] = U32AT(&PL[(r0 + g + 8) * ALD + k0 + 8 + 2 * tig]);
#pragma unroll
                for (int ni = 0; ni < 2; ++ni) {
                    mma_f16(oacc[mi][ni], ah[0], ah[1], ah[2], ah[3], bhv[ni][0], bhv[ni][1]);
                    mma_f16(oacc[mi][ni], ah[0], ah[1], ah[2], ah[3], blv[ni][0], blv[ni][1]);
                    mma_f16(oacc[mi][ni], al[0], al[1], al[2], al[3], bhv[ni][0], bhv[ni][1]);
                }
            }
        }
    }

    // ---- epilogue: write context ----
    float* Cg = g_C + ((size_t)(b * SS + q0)) * DD + h * DK;
#pragma unroll
    for (int mi = 0; mi < 4; ++mi)
#pragma unroll
        for (int ni = 0; ni < 2; ++ni) {
            const int col = wn + ni * 8 + 2 * tig;
            const int r0 = wm + mi * 16 + g;
            *(float2*)(Cg + (size_t)r0 * DD + col) =
                make_float2(oacc[mi][ni][0], oacc[mi][ni][1]);
            *(float2*)(Cg + (size_t)(r0 + 8) * DD + col) =
                make_float2(oacc[mi][ni][2], oacc[mi][ni][3]);
        }
}

// ---------------- launch ------------------------------------------------------
extern "C" void kernel_launch(void* const* d_in, const int* in_sizes, int n_in,
                              void* d_out, int out_size) {
    (void)in_sizes; (void)n_in; (void)out_size;
    const float* query = (const float*)d_in[0];
    const float* key   = (const float*)d_in[1];
    const float* value = (const float*)d_in[2];
    const float* Wq = (const float*)d_in[3];
    const float* bq = (const float*)d_in[4];
    const float* Wk = (const float*)d_in[5];
    const float* bk = (const float*)d_in[6];
    const float* Wv = (const float*)d_in[7];
    const float* bv = (const float*)d_in[8];
    const float* Wo = (const float*)d_in[9];
    const float* bo = (const float*)d_in[10];

    float* out = (float*)d_out;
    float* atp = out + (size_t)BB * SS * DD;

    float *Qp, *Kp, *Vp, *Cp;
    cudaGetSymbolAddress((void**)&Qp, g_Q);
    cudaGetSymbolAddress((void**)&Kp, g_K);
    cudaGetSymbolAddress((void**)&Vp, g_V);
    cudaGetSymbolAddress((void**)&Cp, g_C);

    zero_atp_kernel<<<(BB*SS + 255) / 256, 256>>>(atp);

    cudaFuncSetAttribute(gemm_h, cudaFuncAttributeMaxDynamicSharedMemorySize,
                         GEMM_SMEM);
    cudaFuncSetAttribute(attn_mma, cudaFuncAttributeMaxDynamicSharedMemorySize,
                         AT_SMEM);

    dim3 gg(GN / 128, MTOT / 128);
    gemm_h<<<gg, 256, GEMM_SMEM>>>(query, Wq, bq, Qp);
    gemm_h<<<gg, 256, GEMM_SMEM>>>(key,   Wk, bk, Kp);
    gemm_h<<<gg, 256, GEMM_SMEM>>>(value, Wv, bv, Vp);

    attn_mma<<<dim3(16, 32), 256, AT_SMEM>>>(atp);

    gemm_h<<<gg, 256, GEMM_SMEM>>>(Cp, Wo, bo, out);
}